// round 11
// baseline (speedup 1.0000x reference)
#include <cuda_runtime.h>
#include <cuda_fp16.h>
#include <cstdint>
#include <cstddef>
#include <math.h>

#define THREADS 384
#define MROWS   96

// smem byte offsets (dynamic)
#define OFF_X     0        // 96*3*4 = 1152
#define OFF_W1P   1152     // 4096
#define OFF_WC    5248     // 4096
#define OFF_ZP    9344     // 4 cg * 96 * 16 = 6144
#define OFF_A     15872    // 96 rows * 512 B = 49152
#define OFF_B     65024    // 2 bufs * 36864
#define BROW      144      // 128B data + 16B pad
#define BBUF      36864    // 256 * 144
#define SMEM_TOTAL 138752

__device__ __half g_w2h[65536];

__device__ __forceinline__ uint32_t smem_u32(const void* p) {
    uint32_t a;
    asm("{ .reg .u64 t; cvta.to.shared.u64 t, %1; cvt.u32.u64 %0, t; }" : "=r"(a) : "l"(p));
    return a;
}
__device__ __forceinline__ void cp_async16(uint32_t dst, const void* src) {
    asm volatile("cp.async.cg.shared.global [%0], [%1], 16;" :: "r"(dst), "l"(src) : "memory");
}
__device__ __forceinline__ void cp_commit() { asm volatile("cp.async.commit_group;" ::: "memory"); }
__device__ __forceinline__ void cp_wait1()  { asm volatile("cp.async.wait_group 1;" ::: "memory"); }
__device__ __forceinline__ void cp_wait0()  { asm volatile("cp.async.wait_group 0;" ::: "memory"); }

__device__ __forceinline__ void ldsm_x4(uint32_t* r, uint32_t addr) {
    asm volatile("ldmatrix.sync.aligned.m8n8.x4.shared.b16 {%0,%1,%2,%3}, [%4];"
                 : "=r"(r[0]), "=r"(r[1]), "=r"(r[2]), "=r"(r[3]) : "r"(addr));
}
__device__ __forceinline__ void mma_f16(float* d, const uint32_t* a, uint32_t b0, uint32_t b1) {
    asm volatile(
        "mma.sync.aligned.m16n8k16.row.col.f32.f16.f16.f32 "
        "{%0,%1,%2,%3}, {%4,%5,%6,%7}, {%8,%9}, {%0,%1,%2,%3};"
        : "+f"(d[0]), "+f"(d[1]), "+f"(d[2]), "+f"(d[3])
        : "r"(a[0]), "r"(a[1]), "r"(a[2]), "r"(a[3]), "r"(b0), "r"(b1));
}

// ---------------- pre-kernel: convert w2 to fp16 ----------------
__global__ void w2_half_kernel(const float* __restrict__ w2) {
    int i = blockIdx.x * 256 + threadIdx.x;
    g_w2h[i] = __float2half_rn(w2[i]);
}

// ---------------- main fused kernel ----------------
__global__ __launch_bounds__(THREADS, 1)
void dpl_hmma_kernel(const float* __restrict__ x,
                     const float* __restrict__ w1,
                     const float* __restrict__ b1,
                     const float* __restrict__ b2,
                     const float* __restrict__ w3,
                     const float* __restrict__ b3,
                     float* __restrict__ out,
                     int Btot, int write_logits)
{
    extern __shared__ char smc[];
    const uint32_t smu = smem_u32(smc);
    const int tid  = threadIdx.x;
    const int wid  = tid >> 5;       // 0..11
    const int lane = tid & 31;
    const int row0 = blockIdx.x * MROWS;

    const int rg  = wid % 3;         // row group: rows rg*32..+31
    const int cg  = wid / 3;         // col group: cols cg*64..+63
    const int g   = lane >> 2;       // 0..7
    const int tig = lane & 3;        // 0..3

    // ---- stage params + x ----
    {
        float* sX = (float*)(smc + OFF_X);
        for (int i = tid; i < MROWS * 3; i += THREADS) {
            long gi = (long)row0 * 3 + i;
            sX[i] = (gi < (long)Btot * 3) ? x[gi] : 0.0f;
        }
        if (tid < 256) {
            ((float4*)(smc + OFF_W1P))[tid] =
                make_float4(w1[tid*3+0], w1[tid*3+1], w1[tid*3+2], b1[tid]);
            ((float4*)(smc + OFF_WC))[tid] =
                make_float4(b2[tid], w3[tid], w3[256+tid], w3[512+tid]);
        }
    }
    __syncthreads();

    // ---- preload B chunk 0 (overlaps with layer1) ----
    {
        #pragma unroll
        for (int it = 0; it < 6; it++) {
            int idx = tid + it * THREADS;     // 0..2303, guard at 2048
            if (idx < 2048) {
                int n   = idx >> 3;
                int seg = idx & 7;
                cp_async16(smu + OFF_B + (uint32_t)(n * BROW + seg * 16),
                           (const char*)g_w2h + (size_t)n * 512 + seg * 16);
            }
        }
        cp_commit();
    }

    // ---- layer 1 -> A fp16 tile (XOR-swizzled): 4 threads per row ----
    {
        const float*  sX   = (const float*)(smc + OFF_X);
        const float4* sW1P = (const float4*)(smc + OFF_W1P);
        const int r = tid >> 2;                   // 0..95
        const int quarter = (tid & 3) * 64;
        const uint32_t xorv = (uint32_t)((r & 7) << 4);
        const float x0 = sX[r*3+0], x1 = sX[r*3+1], x2 = sX[r*3+2];
        char* rowp = smc + OFF_A + r * 512;
        #pragma unroll 8
        for (int jp = 0; jp < 32; jp++) {
            const int j = quarter + jp * 2;
            float4 wa = sW1P[j];
            float4 wb = sW1P[j+1];
            float f0 = fmaf(x0, wa.x, fmaf(x1, wa.y, fmaf(x2, wa.z, wa.w)));
            float f1 = fmaf(x0, wb.x, fmaf(x1, wb.y, fmaf(x2, wb.z, wb.w)));
            f0 = fmaxf(f0, 0.0f); f1 = fmaxf(f1, 0.0f);
            __half2 hw = __floats2half2_rn(f0, f1);
            const uint32_t off = (uint32_t)(j * 2) ^ xorv;
            *(uint32_t*)(rowp + off) = *(uint32_t*)&hw;
        }
    }

    // ---- accumulators ----
    float acc[2][8][4];
    #pragma unroll
    for (int mt = 0; mt < 2; mt++)
        #pragma unroll
        for (int nt = 0; nt < 8; nt++)
            #pragma unroll
            for (int q = 0; q < 4; q++) acc[mt][nt][q] = 0.0f;

    // ---- per-lane ldmatrix addresses ----
    const int arow = rg * 32 + (lane & 15);
    const uint32_t aklane = (uint32_t)((lane >> 4) * 16);
    const uint32_t av = (uint32_t)((lane & 7) << 4);
    const uint32_t abase0 = smu + OFF_A + (uint32_t)(arow * 512);
    const uint32_t abase1 = abase0 + 16 * 512;
    const int bm = lane >> 3;          // 0:even-lo,1:even-hi,2:odd-lo,3:odd-hi
    const int bmrow = lane & 7;
    uint32_t boff[4];
    #pragma unroll
    for (int p = 0; p < 4; p++) {
        const int nt = p * 2 + (bm >> 1);
        const int ncol = cg * 64 + nt * 8 + bmrow;
        boff[p] = (uint32_t)(ncol * BROW + (bm & 1) * 16);
    }

    // ---- main loop: 4 chunks of k=64, 2-stage fragment pipeline inside ----
    uint32_t a0[2][4], a1[2][4], bfr[2][4][4];

    for (int c = 0; c < 4; c++) {
        if (c < 3) {
            const int nxt = c + 1;
            #pragma unroll
            for (int it = 0; it < 6; it++) {
                int idx = tid + it * THREADS;
                if (idx < 2048) {
                    int n   = idx >> 3;
                    int seg = idx & 7;
                    cp_async16(smu + OFF_B + (uint32_t)((nxt & 1) * BBUF + n * BROW + seg * 16),
                               (const char*)g_w2h + (size_t)n * 512 + nxt * 128 + seg * 16);
                }
            }
            cp_commit();
            cp_wait1();
        } else {
            cp_wait0();
        }
        __syncthreads();

        const uint32_t bbase = smu + OFF_B + (uint32_t)((c & 1) * BBUF);
        const uint32_t kc = (uint32_t)(c * 128);

        // prologue: load ks=0 fragments into buffer 0
        {
            const uint32_t aoff = (kc + 0 + aklane) ^ av;
            ldsm_x4(a0[0], abase0 + aoff);
            ldsm_x4(a1[0], abase1 + aoff);
            ldsm_x4(bfr[0][0], bbase + boff[0] + 0);
            ldsm_x4(bfr[0][1], bbase + boff[1] + 0);
            ldsm_x4(bfr[0][2], bbase + boff[2] + 0);
            ldsm_x4(bfr[0][3], bbase + boff[3] + 0);
        }

        #pragma unroll
        for (int ks = 0; ks < 4; ks++) {
            const int cur = ks & 1;
            const int nx  = cur ^ 1;
            if (ks < 3) {
                // prefetch next kstep's fragments (independent of current MMAs)
                const uint32_t kbn = (uint32_t)((ks + 1) * 32);
                const uint32_t aoffn = (kc + kbn + aklane) ^ av;
                ldsm_x4(a0[nx], abase0 + aoffn);
                ldsm_x4(a1[nx], abase1 + aoffn);
                ldsm_x4(bfr[nx][0], bbase + boff[0] + kbn);
                ldsm_x4(bfr[nx][1], bbase + boff[1] + kbn);
                ldsm_x4(bfr[nx][2], bbase + boff[2] + kbn);
                ldsm_x4(bfr[nx][3], bbase + boff[3] + kbn);
            }
            #pragma unroll
            for (int p = 0; p < 4; p++) {
                mma_f16(acc[0][p*2  ], a0[cur], bfr[cur][p][0], bfr[cur][p][1]);
                mma_f16(acc[1][p*2  ], a1[cur], bfr[cur][p][0], bfr[cur][p][1]);
                mma_f16(acc[0][p*2+1], a0[cur], bfr[cur][p][2], bfr[cur][p][3]);
                mma_f16(acc[1][p*2+1], a1[cur], bfr[cur][p][2], bfr[cur][p][3]);
            }
        }
        __syncthreads();
    }

    // ---- epilogue: relu(+b2) + layer3 partials in registers ----
    const float4* sWC = (const float4*)(smc + OFF_WC);
    float z[4][3];
    #pragma unroll
    for (int i = 0; i < 4; i++) { z[i][0] = 0.f; z[i][1] = 0.f; z[i][2] = 0.f; }

    #pragma unroll
    for (int mt = 0; mt < 2; mt++) {
        #pragma unroll
        for (int nt = 0; nt < 8; nt++) {
            const int j0 = cg * 64 + nt * 8 + tig * 2;
            float4 wc0 = sWC[j0];
            float4 wc1 = sWC[j0 + 1];
            float h;
            h = fmaxf(acc[mt][nt][0] + wc0.x, 0.0f);
            z[mt*2][0] = fmaf(h, wc0.y, z[mt*2][0]);
            z[mt*2][1] = fmaf(h, wc0.z, z[mt*2][1]);
            z[mt*2][2] = fmaf(h, wc0.w, z[mt*2][2]);
            h = fmaxf(acc[mt][nt][1] + wc1.x, 0.0f);
            z[mt*2][0] = fmaf(h, wc1.y, z[mt*2][0]);
            z[mt*2][1] = fmaf(h, wc1.z, z[mt*2][1]);
            z[mt*2][2] = fmaf(h, wc1.w, z[mt*2][2]);
            h = fmaxf(acc[mt][nt][2] + wc0.x, 0.0f);
            z[mt*2+1][0] = fmaf(h, wc0.y, z[mt*2+1][0]);
            z[mt*2+1][1] = fmaf(h, wc0.z, z[mt*2+1][1]);
            z[mt*2+1][2] = fmaf(h, wc0.w, z[mt*2+1][2]);
            h = fmaxf(acc[mt][nt][3] + wc1.x, 0.0f);
            z[mt*2+1][0] = fmaf(h, wc1.y, z[mt*2+1][0]);
            z[mt*2+1][1] = fmaf(h, wc1.z, z[mt*2+1][1]);
            z[mt*2+1][2] = fmaf(h, wc1.w, z[mt*2+1][2]);
        }
    }
    // reduce across the 4 tig lanes of each quad
    #pragma unroll
    for (int i = 0; i < 4; i++)
        #pragma unroll
        for (int cmp = 0; cmp < 3; cmp++) {
            float v = z[i][cmp];
            v += __shfl_xor_sync(0xffffffffu, v, 1);
            v += __shfl_xor_sync(0xffffffffu, v, 2);
            z[i][cmp] = v;
        }

    if (tig == 0) {
        float4* sZP = (float4*)(smc + OFF_ZP);
        #pragma unroll
        for (int i = 0; i < 4; i++) {
            const int r = rg * 32 + (i >> 1) * 16 + (i & 1) * 8 + g;
            sZP[cg * MROWS + r] = make_float4(z[i][0], z[i][1], z[i][2], 0.0f);
        }
    }
    __syncthreads();

    if (tid < MROWS) {
        const float4* sZP = (const float4*)(smc + OFF_ZP);
        float4 p0 = sZP[tid], p1 = sZP[96 + tid], p2 = sZP[192 + tid], p3 = sZP[288 + tid];
        float z0 = p0.x + p1.x + p2.x + p3.x + b3[0];
        float z1 = p0.y + p1.y + p2.y + p3.y + b3[1];
        float z2 = p0.z + p1.z + p2.z + p3.z + b3[2];

        const int gr = row0 + tid;
        if (gr < Btot) {
            const float eps  = 1e-5f;
            const float norm = 1.0f / (1.0f + 2.0f * eps);
            float s0 = 1.0f / (1.0f + expf(-z0));
            float s1 = 1.0f / (1.0f + expf(-z1));
            float s2 = 1.0f / (1.0f + expf(-z2));
            float pp0 = (s0 + eps) * norm, pn0 = (1.0f - s0 + eps) * norm;
            float pp1 = (s1 + eps) * norm, pn1 = (1.0f - s1 + eps) * norm;
            float pp2 = (s2 + eps) * norm, pn2 = (1.0f - s2 + eps) * norm;
            float pred1 = pn0*pn1*pp2 + pn0*pp1*pn2 + pp0*pn1*pn2 + pp0*pp1*pp2;
            float pred0 = 1.0f - pred1;
            const float onorm = 1.0f / 1.002f;
            float2 pr = make_float2((pred0 + 0.001f) * onorm, (pred1 + 0.001f) * onorm);
            *(float2*)&out[(size_t)gr * 2] = pr;
            if (write_logits) {
                float* outLg = &out[(size_t)2 * Btot + (size_t)gr * 3];
                outLg[0] = z0; outLg[1] = z1; outLg[2] = z2;
            }
        }
    }
}

extern "C" void kernel_launch(void* const* d_in, const int* in_sizes, int n_in,
                              void* d_out, int out_size)
{
    const float* x  = (const float*)d_in[0];
    const float* w1 = (const float*)d_in[1];
    const float* b1 = (const float*)d_in[2];
    const float* w2 = (const float*)d_in[3];
    const float* b2 = (const float*)d_in[4];
    const float* w3 = (const float*)d_in[5];
    const float* b3 = (const float*)d_in[6];
    float* out = (float*)d_out;

    const int B = in_sizes[0] / 3;
    const int write_logits = (out_size >= 5 * B) ? 1 : 0;

    w2_half_kernel<<<256, 256>>>(w2);

    cudaFuncSetAttribute(dpl_hmma_kernel,
                         cudaFuncAttributeMaxDynamicSharedMemorySize, SMEM_TOTAL);

    const int grid = (B + MROWS - 1) / MROWS;
    dpl_hmma_kernel<<<grid, THREADS, SMEM_TOTAL>>>(x, w1, b1, b2, w3, b3,
                                                   out, B, write_logits);
}

// round 12
// speedup vs baseline: 2.4631x; 2.4631x over previous
#include <cuda_runtime.h>
#include <cuda_fp16.h>
#include <cstdint>
#include <cstddef>
#include <math.h>

#define THREADS 512
#define MROWS   128

// smem byte offsets (dynamic)
#define OFF_X     0        // 1536
#define OFF_W1P   1536     // 4096
#define OFF_WC    5632     // 4096
#define OFF_ZP    9728     // 8192
#define OFF_A     18432    // 128 rows * 512 B = 65536
#define OFF_B     83968    // 256 rows * 528 B = 135168 (full w2 fp16, resident)
#define BROW      528      // 512B data + 16B pad -> conflict-free ldmatrix phases
#define SMEM_TOTAL 219136

__device__ __half g_w2h[65536];

__device__ __forceinline__ uint32_t smem_u32(const void* p) {
    uint32_t a;
    asm("{ .reg .u64 t; cvta.to.shared.u64 t, %1; cvt.u32.u64 %0, t; }" : "=r"(a) : "l"(p));
    return a;
}
__device__ __forceinline__ void cp_async16(uint32_t dst, const void* src) {
    asm volatile("cp.async.cg.shared.global [%0], [%1], 16;" :: "r"(dst), "l"(src) : "memory");
}
__device__ __forceinline__ void cp_commit() { asm volatile("cp.async.commit_group;" ::: "memory"); }
__device__ __forceinline__ void cp_wait0()  { asm volatile("cp.async.wait_group 0;" ::: "memory"); }

__device__ __forceinline__ void ldsm_x4(uint32_t* r, uint32_t addr) {
    asm volatile("ldmatrix.sync.aligned.m8n8.x4.shared.b16 {%0,%1,%2,%3}, [%4];"
                 : "=r"(r[0]), "=r"(r[1]), "=r"(r[2]), "=r"(r[3]) : "r"(addr));
}
__device__ __forceinline__ void mma_f16(float* d, const uint32_t* a, uint32_t b0, uint32_t b1) {
    asm volatile(
        "mma.sync.aligned.m16n8k16.row.col.f32.f16.f16.f32 "
        "{%0,%1,%2,%3}, {%4,%5,%6,%7}, {%8,%9}, {%0,%1,%2,%3};"
        : "+f"(d[0]), "+f"(d[1]), "+f"(d[2]), "+f"(d[3])
        : "r"(a[0]), "r"(a[1]), "r"(a[2]), "r"(a[3]), "r"(b0), "r"(b1));
}

// ---------------- pre-kernel: convert w2 to fp16 ----------------
__global__ void w2_half_kernel(const float* __restrict__ w2) {
    int i = blockIdx.x * 256 + threadIdx.x;
    g_w2h[i] = __float2half_rn(w2[i]);
}

// ---------------- main fused persistent kernel ----------------
__global__ __launch_bounds__(THREADS, 1)
void dpl_hmma_kernel(const float* __restrict__ x,
                     const float* __restrict__ w1,
                     const float* __restrict__ b1,
                     const float* __restrict__ b2,
                     const float* __restrict__ w3,
                     const float* __restrict__ b3,
                     float* __restrict__ out,
                     int Btot, int write_logits)
{
    extern __shared__ char smc[];
    const uint32_t smu = smem_u32(smc);
    const int tid  = threadIdx.x;
    const int wid  = tid >> 5;
    const int lane = tid & 31;

    const int rg  = wid & 3;       // row group: rows rg*32..+31
    const int cg  = wid >> 2;      // col group: cols cg*64..+63
    const int g   = lane >> 2;     // 0..7
    const int tig = lane & 3;      // 0..3

    // ---- issue full B (128 KB) via cp.async; hidden behind first tile's layer1 ----
    {
        #pragma unroll
        for (int it = 0; it < 16; it++) {
            int idx = tid + it * THREADS;     // 0..8191
            int n   = idx >> 5;               // 0..255
            int seg = idx & 31;
            cp_async16(smu + OFF_B + (uint32_t)(n * BROW + seg * 16),
                       (const char*)g_w2h + (size_t)n * 512 + seg * 16);
        }
        cp_commit();
    }

    // ---- stage constant params once ----
    if (tid < 256) {
        ((float4*)(smc + OFF_W1P))[tid] =
            make_float4(w1[tid*3+0], w1[tid*3+1], w1[tid*3+2], b1[tid]);
        ((float4*)(smc + OFF_WC))[tid] =
            make_float4(b2[tid], w3[tid], w3[256+tid], w3[512+tid]);
    }
    const float b30 = b3[0], b31 = b3[1], b32 = b3[2];

    // ---- per-lane ldmatrix addresses (tile-invariant) ----
    const int arow = rg * 32 + (lane & 15);
    const uint32_t aklane = (uint32_t)((lane >> 4) * 16);
    const uint32_t av = (uint32_t)((lane & 7) << 4);
    const uint32_t abase0 = smu + OFF_A + (uint32_t)(arow * 512);
    const uint32_t abase1 = abase0 + 16 * 512;
    const int bm = lane >> 3;          // 0:even-lo,1:even-hi,2:odd-lo,3:odd-hi
    const int bmrow = lane & 7;
    uint32_t bbase[4];
    #pragma unroll
    for (int p = 0; p < 4; p++) {
        const int nt = p * 2 + (bm >> 1);
        const int ncol = cg * 64 + nt * 8 + bmrow;
        bbase[p] = smu + OFF_B + (uint32_t)(ncol * BROW + (bm & 1) * 16);
    }

    const int ntiles = (Btot + MROWS - 1) / MROWS;
    bool b_pending = true;

    for (int t = blockIdx.x; t < ntiles; t += gridDim.x) {
        const int row0 = t * MROWS;

        // ---- stage x tile ----
        {
            float* sX = (float*)(smc + OFF_X);
            for (int i = tid; i < MROWS * 3; i += THREADS) {
                long gi = (long)row0 * 3 + i;
                sX[i] = (gi < (long)Btot * 3) ? x[gi] : 0.0f;
            }
        }
        __syncthreads();   // sync(1): x (and W1P on first tile) visible

        // ---- layer 1 -> A fp16 tile (XOR-swizzled) ----
        {
            const float*  sX   = (const float*)(smc + OFF_X);
            const float4* sW1P = (const float4*)(smc + OFF_W1P);
            const int rb = (wid & 3) * 32 + (lane & 7);
            const int jb = (wid >> 2) * 64 + ((lane >> 3) << 1);
            const uint32_t xorv = (uint32_t)((lane & 7) << 4);
            #pragma unroll
            for (int s = 0; s < 4; s++) {
                const int r = rb + s * 8;
                const float x0 = sX[r*3+0], x1 = sX[r*3+1], x2 = sX[r*3+2];
                char* rowp = smc + OFF_A + r * 512;
                #pragma unroll
                for (int tt = 0; tt < 8; tt++) {
                    const int j = jb + tt * 8;
                    float4 wa = sW1P[j];
                    float4 wb = sW1P[j+1];
                    float f0 = fmaf(x0, wa.x, fmaf(x1, wa.y, fmaf(x2, wa.z, wa.w)));
                    float f1 = fmaf(x0, wb.x, fmaf(x1, wb.y, fmaf(x2, wb.z, wb.w)));
                    f0 = fmaxf(f0, 0.0f); f1 = fmaxf(f1, 0.0f);
                    __half2 hw = __floats2half2_rn(f0, f1);
                    const uint32_t off = (uint32_t)(j * 2) ^ xorv;
                    *(uint32_t*)(rowp + off) = *(uint32_t*)&hw;
                }
            }
        }
        if (b_pending) { cp_wait0(); b_pending = false; }
        __syncthreads();   // sync(2): A tile (and B on first tile) ready

        // ---- accumulators ----
        float acc[2][8][4];
        #pragma unroll
        for (int mt = 0; mt < 2; mt++)
            #pragma unroll
            for (int nt = 0; nt < 8; nt++)
                #pragma unroll
                for (int q = 0; q < 4; q++) acc[mt][nt][q] = 0.0f;

        // ---- mainloop: 16 ksteps, no barriers, no async traffic ----
        #pragma unroll 4
        for (int ks = 0; ks < 16; ks++) {
            const uint32_t kb = (uint32_t)(ks * 32);
            const uint32_t aoff = (kb + aklane) ^ av;

            uint32_t a0[4], a1[4];
            ldsm_x4(a0, abase0 + aoff);
            ldsm_x4(a1, abase1 + aoff);

            uint32_t bfr[4][4];
            ldsm_x4(bfr[0], bbase[0] + kb);
            ldsm_x4(bfr[1], bbase[1] + kb);
            ldsm_x4(bfr[2], bbase[2] + kb);
            ldsm_x4(bfr[3], bbase[3] + kb);

            #pragma unroll
            for (int p = 0; p < 4; p++) {
                mma_f16(acc[0][p*2  ], a0, bfr[p][0], bfr[p][1]);
                mma_f16(acc[1][p*2  ], a1, bfr[p][0], bfr[p][1]);
                mma_f16(acc[0][p*2+1], a0, bfr[p][2], bfr[p][3]);
                mma_f16(acc[1][p*2+1], a1, bfr[p][2], bfr[p][3]);
            }
        }

        // ---- epilogue: relu(+b2) + layer3 partials ----
        const float4* sWC = (const float4*)(smc + OFF_WC);
        float z[4][3];
        #pragma unroll
        for (int i = 0; i < 4; i++) { z[i][0] = 0.f; z[i][1] = 0.f; z[i][2] = 0.f; }

        #pragma unroll
        for (int mt = 0; mt < 2; mt++) {
            #pragma unroll
            for (int nt = 0; nt < 8; nt++) {
                const int j0 = cg * 64 + nt * 8 + tig * 2;
                float4 wc0 = sWC[j0];
                float4 wc1 = sWC[j0 + 1];
                float h;
                h = fmaxf(acc[mt][nt][0] + wc0.x, 0.0f);
                z[mt*2][0] = fmaf(h, wc0.y, z[mt*2][0]);
                z[mt*2][1] = fmaf(h, wc0.z, z[mt*2][1]);
                z[mt*2][2] = fmaf(h, wc0.w, z[mt*2][2]);
                h = fmaxf(acc[mt][nt][1] + wc1.x, 0.0f);
                z[mt*2][0] = fmaf(h, wc1.y, z[mt*2][0]);
                z[mt*2][1] = fmaf(h, wc1.z, z[mt*2][1]);
                z[mt*2][2] = fmaf(h, wc1.w, z[mt*2][2]);
                h = fmaxf(acc[mt][nt][2] + wc0.x, 0.0f);
                z[mt*2+1][0] = fmaf(h, wc0.y, z[mt*2+1][0]);
                z[mt*2+1][1] = fmaf(h, wc0.z, z[mt*2+1][1]);
                z[mt*2+1][2] = fmaf(h, wc0.w, z[mt*2+1][2]);
                h = fmaxf(acc[mt][nt][3] + wc1.x, 0.0f);
                z[mt*2+1][0] = fmaf(h, wc1.y, z[mt*2+1][0]);
                z[mt*2+1][1] = fmaf(h, wc1.z, z[mt*2+1][1]);
                z[mt*2+1][2] = fmaf(h, wc1.w, z[mt*2+1][2]);
            }
        }
        #pragma unroll
        for (int i = 0; i < 4; i++)
            #pragma unroll
            for (int cmp = 0; cmp < 3; cmp++) {
                float v = z[i][cmp];
                v += __shfl_xor_sync(0xffffffffu, v, 1);
                v += __shfl_xor_sync(0xffffffffu, v, 2);
                z[i][cmp] = v;
            }

        if (tig == 0) {
            float4* sZP = (float4*)(smc + OFF_ZP);
            #pragma unroll
            for (int i = 0; i < 4; i++) {
                const int r = rg * 32 + (i >> 1) * 16 + (i & 1) * 8 + g;
                sZP[cg * 128 + r] = make_float4(z[i][0], z[i][1], z[i][2], 0.0f);
            }
        }
        __syncthreads();   // sync(3): partials visible

        if (tid < MROWS) {
            const float4* sZP = (const float4*)(smc + OFF_ZP);
            float4 p0 = sZP[tid], p1 = sZP[128 + tid], p2 = sZP[256 + tid], p3 = sZP[384 + tid];
            float z0 = p0.x + p1.x + p2.x + p3.x + b30;
            float z1 = p0.y + p1.y + p2.y + p3.y + b31;
            float z2 = p0.z + p1.z + p2.z + p3.z + b32;

            const int gr = row0 + tid;
            if (gr < Btot) {
                const float eps  = 1e-5f;
                const float norm = 1.0f / (1.0f + 2.0f * eps);
                float s0 = 1.0f / (1.0f + expf(-z0));
                float s1 = 1.0f / (1.0f + expf(-z1));
                float s2 = 1.0f / (1.0f + expf(-z2));
                float pp0 = (s0 + eps) * norm, pn0 = (1.0f - s0 + eps) * norm;
                float pp1 = (s1 + eps) * norm, pn1 = (1.0f - s1 + eps) * norm;
                float pp2 = (s2 + eps) * norm, pn2 = (1.0f - s2 + eps) * norm;
                float pred1 = pn0*pn1*pp2 + pn0*pp1*pn2 + pp0*pn1*pn2 + pp0*pp1*pp2;
                float pred0 = 1.0f - pred1;
                const float onorm = 1.0f / 1.002f;
                float2 pr = make_float2((pred0 + 0.001f) * onorm, (pred1 + 0.001f) * onorm);
                *(float2*)&out[(size_t)gr * 2] = pr;
                if (write_logits) {
                    float* outLg = &out[(size_t)2 * Btot + (size_t)gr * 3];
                    outLg[0] = z0; outLg[1] = z1; outLg[2] = z2;
                }
            }
        }
        __syncthreads();   // sync(4): sZP reads done before next tile reuses smem phases
    }
}

extern "C" void kernel_launch(void* const* d_in, const int* in_sizes, int n_in,
                              void* d_out, int out_size)
{
    const float* x  = (const float*)d_in[0];
    const float* w1 = (const float*)d_in[1];
    const float* b1 = (const float*)d_in[2];
    const float* w2 = (const float*)d_in[3];
    const float* b2 = (const float*)d_in[4];
    const float* w3 = (const float*)d_in[5];
    const float* b3 = (const float*)d_in[6];
    float* out = (float*)d_out;

    const int B = in_sizes[0] / 3;
    const int write_logits = (out_size >= 5 * B) ? 1 : 0;

    w2_half_kernel<<<256, 256>>>(w2);

    cudaFuncSetAttribute(dpl_hmma_kernel,
                         cudaFuncAttributeMaxDynamicSharedMemorySize, SMEM_TOTAL);

    int dev = 0, nsm = 148;
    cudaGetDevice(&dev);
    cudaDeviceGetAttribute(&nsm, cudaDevAttrMultiProcessorCount, dev);

    dpl_hmma_kernel<<<nsm, THREADS, SMEM_TOTAL>>>(x, w1, b1, b2, w3, b3,
                                                  out, B, write_logits);
}

// round 13
// speedup vs baseline: 2.4870x; 1.0097x over previous
#include <cuda_runtime.h>
#include <cuda_fp16.h>
#include <cstdint>
#include <cstddef>
#include <math.h>

#define THREADS 512
#define MROWS   128

// smem byte offsets (dynamic)
#define OFF_X0    0        // 1536
#define OFF_X1    1536     // 1536
#define OFF_W1P   3072     // 4096
#define OFF_WC    7168     // 4096
#define OFF_ZP    11264    // 8192
#define OFF_A     19456    // 128 rows * 512 B = 65536 (1024-aligned)
#define OFF_B     84992    // 256 rows * 528 B = 135168 (1024-aligned)
#define BROW      528
#define SMEM_TOTAL 220160

__device__ __half g_w2h[65536];

__device__ __forceinline__ uint32_t smem_u32(const void* p) {
    uint32_t a;
    asm("{ .reg .u64 t; cvta.to.shared.u64 t, %1; cvt.u32.u64 %0, t; }" : "=r"(a) : "l"(p));
    return a;
}
__device__ __forceinline__ void cp_async16(uint32_t dst, const void* src) {
    asm volatile("cp.async.cg.shared.global [%0], [%1], 16;" :: "r"(dst), "l"(src) : "memory");
}
__device__ __forceinline__ void cp_commit() { asm volatile("cp.async.commit_group;" ::: "memory"); }
__device__ __forceinline__ void cp_wait1()  { asm volatile("cp.async.wait_group 1;" ::: "memory"); }
__device__ __forceinline__ void cp_wait0()  { asm volatile("cp.async.wait_group 0;" ::: "memory"); }

__device__ __forceinline__ void ldsm_x4(uint32_t* r, uint32_t addr) {
    asm volatile("ldmatrix.sync.aligned.m8n8.x4.shared.b16 {%0,%1,%2,%3}, [%4];"
                 : "=r"(r[0]), "=r"(r[1]), "=r"(r[2]), "=r"(r[3]) : "r"(addr));
}
__device__ __forceinline__ void mma_f16(float* d, const uint32_t* a, uint32_t b0, uint32_t b1) {
    asm volatile(
        "mma.sync.aligned.m16n8k16.row.col.f32.f16.f16.f32 "
        "{%0,%1,%2,%3}, {%4,%5,%6,%7}, {%8,%9}, {%0,%1,%2,%3};"
        : "+f"(d[0]), "+f"(d[1]), "+f"(d[2]), "+f"(d[3])
        : "r"(a[0]), "r"(a[1]), "r"(a[2]), "r"(a[3]), "r"(b0), "r"(b1));
}

// ---------------- pre-kernel: convert w2 to fp16 ----------------
__global__ void w2_half_kernel(const float* __restrict__ w2) {
    int i = blockIdx.x * 256 + threadIdx.x;
    g_w2h[i] = __float2half_rn(w2[i]);
}

// ---------------- main fused persistent kernel ----------------
__global__ __launch_bounds__(THREADS, 1)
void dpl_hmma_kernel(const float* __restrict__ x,
                     const float* __restrict__ w1,
                     const float* __restrict__ b1,
                     const float* __restrict__ b2,
                     const float* __restrict__ w3,
                     const float* __restrict__ b3,
                     float* __restrict__ out,
                     int Btot, int write_logits)
{
    extern __shared__ char smc[];
    const uint32_t smu = smem_u32(smc);
    const int tid  = threadIdx.x;
    const int wid  = tid >> 5;
    const int lane = tid & 31;

    const int rg  = wid & 3;       // row group: rows rg*32..+31 (also = SMSP id)
    const int cg  = wid >> 2;      // col group: cols cg*64..+63
    const int g   = lane >> 2;     // 0..7
    const int tig = lane & 3;      // 0..3

    const int ntiles = (Btot + MROWS - 1) / MROWS;
    const int t0 = blockIdx.x;

    // ---- prologue: prefetch x(t0) [group 1], then full B [group 2] ----
    if (t0 < ntiles && (t0 * MROWS + MROWS) <= Btot && tid < 96) {
        cp_async16(smu + OFF_X0 + (uint32_t)(tid * 16),
                   (const char*)x + (size_t)t0 * MROWS * 12 + tid * 16);
    }
    cp_commit();
    {
        #pragma unroll
        for (int it = 0; it < 16; it++) {
            int idx = tid + it * THREADS;
            int n   = idx >> 5;
            int seg = idx & 31;
            cp_async16(smu + OFF_B + (uint32_t)(n * BROW + seg * 16),
                       (const char*)g_w2h + (size_t)n * 512 + seg * 16);
        }
        cp_commit();
    }

    // ---- stage constant params once ----
    if (tid < 256) {
        ((float4*)(smc + OFF_W1P))[tid] =
            make_float4(w1[tid*3+0], w1[tid*3+1], w1[tid*3+2], b1[tid]);
        ((float4*)(smc + OFF_WC))[tid] =
            make_float4(b2[tid], w3[tid], w3[256+tid], w3[512+tid]);
    }
    const float b30 = b3[0], b31 = b3[1], b32 = b3[2];

    // ---- per-lane ldmatrix addresses (tile-invariant) ----
    const int arow = rg * 32 + (lane & 15);
    const uint32_t aklane = (uint32_t)((lane >> 4) * 16);
    const uint32_t av = (uint32_t)((lane & 7) << 4);
    const uint32_t abase0 = smu + OFF_A + (uint32_t)(arow * 512);
    const uint32_t abase1 = abase0 + 16 * 512;
    const int bm = lane >> 3;          // 0:even-lo,1:even-hi,2:odd-lo,3:odd-hi
    const int bmrow = lane & 7;
    uint32_t bbase[4];
    #pragma unroll
    for (int p = 0; p < 4; p++) {
        const int nt = p * 2 + (bm >> 1);
        const int ncol = cg * 64 + nt * 8 + bmrow;
        bbase[p] = smu + OFF_B + (uint32_t)(ncol * BROW + (bm & 1) * 16);
    }
    const int kstag = cg * 4;          // kstep stagger: decorrelate same-SMSP warps

    bool first = true;
    int xcur = 0;

    for (int t = t0; t < ntiles; t += gridDim.x) {
        const int row0 = t * MROWS;
        const uint32_t offX = (xcur ? OFF_X1 : OFF_X0);
        const bool fullTile = (row0 + MROWS) <= Btot;

        if (first) cp_wait1(); else cp_wait0();   // x(t) ready (first: B may pend)
        if (!fullTile) {
            // tail tile was never prefetched: guarded synchronous load
            float* sX = (float*)(smc + offX);
            for (int i = tid; i < MROWS * 3; i += THREADS) {
                long gi = (long)row0 * 3 + i;
                sX[i] = (gi < (long)Btot * 3) ? x[gi] : 0.0f;
            }
        }
        __syncthreads();   // sync(1): x(t) visible (and W1P/WC on first tile)

        // ---- prefetch x(t+grid) into the other buffer ----
        {
            const int tn = t + gridDim.x;
            if (tn < ntiles && (tn * MROWS + MROWS) <= Btot && tid < 96) {
                cp_async16(smu + (xcur ? OFF_X0 : OFF_X1) + (uint32_t)(tid * 16),
                           (const char*)x + (size_t)tn * MROWS * 12 + tid * 16);
            }
            cp_commit();
        }

        // ---- layer 1 -> A fp16 tile (XOR-swizzled) ----
        {
            const float*  sX   = (const float*)(smc + offX);
            const float4* sW1P = (const float4*)(smc + OFF_W1P);
            const int rb = (wid & 3) * 32 + (lane & 7);
            const int jb = (wid >> 2) * 64 + ((lane >> 3) << 1);
            const uint32_t xorv = (uint32_t)((lane & 7) << 4);
            #pragma unroll
            for (int s = 0; s < 4; s++) {
                const int r = rb + s * 8;
                const float x0 = sX[r*3+0], x1 = sX[r*3+1], x2 = sX[r*3+2];
                char* rowp = smc + OFF_A + r * 512;
                #pragma unroll
                for (int tt = 0; tt < 8; tt++) {
                    const int j = jb + tt * 8;
                    float4 wa = sW1P[j];
                    float4 wb = sW1P[j+1];
                    float f0 = fmaf(x0, wa.x, fmaf(x1, wa.y, fmaf(x2, wa.z, wa.w)));
                    float f1 = fmaf(x0, wb.x, fmaf(x1, wb.y, fmaf(x2, wb.z, wb.w)));
                    f0 = fmaxf(f0, 0.0f); f1 = fmaxf(f1, 0.0f);
                    __half2 hw = __floats2half2_rn(f0, f1);
                    const uint32_t off = (uint32_t)(j * 2) ^ xorv;
                    *(uint32_t*)(rowp + off) = *(uint32_t*)&hw;
                }
            }
        }
        if (first) { cp_wait1(); first = false; }   // drain B (allow x-prefetch to pend)
        __syncthreads();   // sync(2): A tile (and B on first tile) ready

        // ---- accumulators ----
        float acc[2][8][4];
        #pragma unroll
        for (int mt = 0; mt < 2; mt++)
            #pragma unroll
            for (int nt = 0; nt < 8; nt++)
                #pragma unroll
                for (int q = 0; q < 4; q++) acc[mt][nt][q] = 0.0f;

        // ---- mainloop: 16 ksteps, staggered start per cg ----
        #pragma unroll 4
        for (int s = 0; s < 16; s++) {
            const int ks = (s + kstag) & 15;
            const uint32_t kb = (uint32_t)(ks * 32);
            const uint32_t aoff = (kb + aklane) ^ av;

            uint32_t a0[4], a1[4];
            ldsm_x4(a0, abase0 + aoff);
            ldsm_x4(a1, abase1 + aoff);

            uint32_t bfr[4][4];
            ldsm_x4(bfr[0], bbase[0] + kb);
            ldsm_x4(bfr[1], bbase[1] + kb);
            ldsm_x4(bfr[2], bbase[2] + kb);
            ldsm_x4(bfr[3], bbase[3] + kb);

            #pragma unroll
            for (int p = 0; p < 4; p++) {
                mma_f16(acc[0][p*2  ], a0, bfr[p][0], bfr[p][1]);
                mma_f16(acc[1][p*2  ], a1, bfr[p][0], bfr[p][1]);
                mma_f16(acc[0][p*2+1], a0, bfr[p][2], bfr[p][3]);
                mma_f16(acc[1][p*2+1], a1, bfr[p][2], bfr[p][3]);
            }
        }

        // ---- epilogue: relu(+b2) + layer3 partials ----
        const float4* sWC = (const float4*)(smc + OFF_WC);
        float z[4][3];
        #pragma unroll
        for (int i = 0; i < 4; i++) { z[i][0] = 0.f; z[i][1] = 0.f; z[i][2] = 0.f; }

        #pragma unroll
        for (int mt = 0; mt < 2; mt++) {
            #pragma unroll
            for (int nt = 0; nt < 8; nt++) {
                const int j0 = cg * 64 + nt * 8 + tig * 2;
                float4 wc0 = sWC[j0];
                float4 wc1 = sWC[j0 + 1];
                float h;
                h = fmaxf(acc[mt][nt][0] + wc0.x, 0.0f);
                z[mt*2][0] = fmaf(h, wc0.y, z[mt*2][0]);
                z[mt*2][1] = fmaf(h, wc0.z, z[mt*2][1]);
                z[mt*2][2] = fmaf(h, wc0.w, z[mt*2][2]);
                h = fmaxf(acc[mt][nt][1] + wc1.x, 0.0f);
                z[mt*2][0] = fmaf(h, wc1.y, z[mt*2][0]);
                z[mt*2][1] = fmaf(h, wc1.z, z[mt*2][1]);
                z[mt*2][2] = fmaf(h, wc1.w, z[mt*2][2]);
                h = fmaxf(acc[mt][nt][2] + wc0.x, 0.0f);
                z[mt*2+1][0] = fmaf(h, wc0.y, z[mt*2+1][0]);
                z[mt*2+1][1] = fmaf(h, wc0.z, z[mt*2+1][1]);
                z[mt*2+1][2] = fmaf(h, wc0.w, z[mt*2+1][2]);
                h = fmaxf(acc[mt][nt][3] + wc1.x, 0.0f);
                z[mt*2+1][0] = fmaf(h, wc1.y, z[mt*2+1][0]);
                z[mt*2+1][1] = fmaf(h, wc1.z, z[mt*2+1][1]);
                z[mt*2+1][2] = fmaf(h, wc1.w, z[mt*2+1][2]);
            }
        }
        #pragma unroll
        for (int i = 0; i < 4; i++)
            #pragma unroll
            for (int cmp = 0; cmp < 3; cmp++) {
                float v = z[i][cmp];
                v += __shfl_xor_sync(0xffffffffu, v, 1);
                v += __shfl_xor_sync(0xffffffffu, v, 2);
                z[i][cmp] = v;
            }

        if (tig == 0) {
            float4* sZP = (float4*)(smc + OFF_ZP);
            #pragma unroll
            for (int i = 0; i < 4; i++) {
                const int r = rg * 32 + (i >> 1) * 16 + (i & 1) * 8 + g;
                sZP[cg * 128 + r] = make_float4(z[i][0], z[i][1], z[i][2], 0.0f);
            }
        }
        __syncthreads();   // sync(3): partials visible

        if (tid < MROWS) {
            const float4* sZP = (const float4*)(smc + OFF_ZP);
            float4 p0 = sZP[tid], p1 = sZP[128 + tid], p2 = sZP[256 + tid], p3 = sZP[384 + tid];
            float z0 = p0.x + p1.x + p2.x + p3.x + b30;
            float z1 = p0.y + p1.y + p2.y + p3.y + b31;
            float z2 = p0.z + p1.z + p2.z + p3.z + b32;

            const int gr = row0 + tid;
            if (gr < Btot) {
                const float eps  = 1e-5f;
                const float norm = 1.0f / (1.0f + 2.0f * eps);
                float s0 = 1.0f / (1.0f + expf(-z0));
                float s1 = 1.0f / (1.0f + expf(-z1));
                float s2 = 1.0f / (1.0f + expf(-z2));
                float pp0 = (s0 + eps) * norm, pn0 = (1.0f - s0 + eps) * norm;
                float pp1 = (s1 + eps) * norm, pn1 = (1.0f - s1 + eps) * norm;
                float pp2 = (s2 + eps) * norm, pn2 = (1.0f - s2 + eps) * norm;
                float pred1 = pn0*pn1*pp2 + pn0*pp1*pn2 + pp0*pn1*pn2 + pp0*pp1*pp2;
                float pred0 = 1.0f - pred1;
                const float onorm = 1.0f / 1.002f;
                float2 pr = make_float2((pred0 + 0.001f) * onorm, (pred1 + 0.001f) * onorm);
                *(float2*)&out[(size_t)gr * 2] = pr;
                if (write_logits) {
                    float* outLg = &out[(size_t)2 * Btot + (size_t)gr * 3];
                    outLg[0] = z0; outLg[1] = z1; outLg[2] = z2;
                }
            }
        }
        // no sync(4): tile t+1's sync(1)/(2) order ZP writes after these reads,
        // and X is double-buffered.
        xcur ^= 1;
    }
}

extern "C" void kernel_launch(void* const* d_in, const int* in_sizes, int n_in,
                              void* d_out, int out_size)
{
    const float* x  = (const float*)d_in[0];
    const float* w1 = (const float*)d_in[1];
    const float* b1 = (const float*)d_in[2];
    const float* w2 = (const float*)d_in[3];
    const float* b2 = (const float*)d_in[4];
    const float* w3 = (const float*)d_in[5];
    const float* b3 = (const float*)d_in[6];
    float* out = (float*)d_out;

    const int B = in_sizes[0] / 3;
    const int write_logits = (out_size >= 5 * B) ? 1 : 0;

    w2_half_kernel<<<256, 256>>>(w2);

    cudaFuncSetAttribute(dpl_hmma_kernel,
                         cudaFuncAttributeMaxDynamicSharedMemorySize, SMEM_TOTAL);

    int dev = 0, nsm = 148;
    cudaGetDevice(&dev);
    cudaDeviceGetAttribute(&nsm, cudaDevAttrMultiProcessorCount, dev);

    dpl_hmma_kernel<<<nsm, THREADS, SMEM_TOTAL>>>(x, w1, b1, b2, w3, b3,
                                                  out, B, write_logits);
}